// round 2
// baseline (speedup 1.0000x reference)
#include <cuda_runtime.h>
#include <math.h>

#define J 23
#define BLK 128
#define VPT 4
#define VPB (BLK * VPT)   // 512 vertices per block

__device__ __constant__ int c_par[J] = {-1, 0, 1, 1, 3, 4, 5, 4, 7, 4, 9, 1, 11, 12, 13, 12, 15, 12, 17, 0, 19, 0, 21};

__global__ __launch_bounds__(BLK) void k_fused(
    const float* __restrict__ vt, const float* __restrict__ skin,
    const float* __restrict__ jr,
    const float* __restrict__ j0, const float* __restrict__ j1,
    const float* __restrict__ j2, const float* __restrict__ j3,
    const float* __restrict__ j4, const float* __restrict__ j5,
    const float* __restrict__ j12, const float* __restrict__ j13,
    const float* __restrict__ la, const float* __restrict__ disp,
    const float* __restrict__ scl, const float* __restrict__ loc,
    float* __restrict__ out,
    int V, int B,
    long long poseOff, long long jointsOff, long long scaleOff,
    long long dispOff, long long laOff)
{
    __shared__ __align__(16) float sW[VPB * J];   // 47104 B
    __shared__ __align__(16) float sA[J * 12];    // blended transforms
    __shared__ float sC[4];                       // c, ox, oy, oz

    const int tid = threadIdx.x;
    const long long vbase = (long long)blockIdx.x * VPB;
    const int nv = min(VPB, V - (int)vbase);
    const float PI = 3.14159265358979323846f;

    // ================= pose / kinematics (warp 0 only) =================
    if (tid < 32) {
        int j = tid;
        float T[12];
        #pragma unroll
        for (int k = 0; k < 12; k++) T[k] = 0.f;

        if (j < J) {
            float amp = 0.f, sy = 1.f, sz = 1.f;
            const float* src = nullptr;
            switch (j) {
                case 0:  amp = PI / 2.f; src = j0;  break;
                case 1:  amp = PI / 4.f; src = j1;  break;
                case 2:  amp = PI / 9.f; src = j2;  break;
                case 3:  amp = PI / 3.f; src = j3;  break;
                case 11: amp = PI / 3.f; src = j3;  sy = -1.f; sz = -1.f; break;
                case 4:  amp = PI / 3.f; src = j4;  break;
                case 5:  amp = PI / 3.f; src = j5;  break;
                case 12: amp = PI / 3.f; src = j12; break;
                case 13: amp = PI / 3.f; src = j13; break;
            }
            float px = 0.f, py = 0.f, pz = 0.f;
            if (src) {
                px = amp * tanhf(src[0]);
                py = amp * sy * tanhf(src[1]);
                pz = amp * sz * tanhf(src[2]);
            }
            if (blockIdx.x == 0) {
                out[poseOff + j * 3 + 0] = px;
                out[poseOff + j * 3 + 1] = py;
                out[poseOff + j * 3 + 2] = pz;
            }

            float ang = sqrtf(px * px + py * py + pz * pz + 1e-12f);
            float inv = 1.f / ang;
            float x = px * inv, y = py * inv, z = pz * inv;
            float s = sinf(ang), c = cosf(ang), t = 1.f - c;

            int p = c_par[j];
            float rx = jr[j * 3 + 0] - (p >= 0 ? jr[p * 3 + 0] : 0.f);
            float ry = jr[j * 3 + 1] - (p >= 0 ? jr[p * 3 + 1] : 0.f);
            float rz = jr[j * 3 + 2] - (p >= 0 ? jr[p * 3 + 2] : 0.f);

            T[0] = 1.f + t * (-(y * y + z * z));
            T[1] = -s * z + t * (x * y);
            T[2] =  s * y + t * (x * z);
            T[3] = rx;
            T[4] =  s * z + t * (x * y);
            T[5] = 1.f + t * (-(x * x + z * z));
            T[6] = -s * x + t * (y * z);
            T[7] = ry;
            T[8] = -s * y + t * (x * z);
            T[9] =  s * x + t * (y * z);
            T[10] = 1.f + t * (-(x * x + y * y));
            T[11] = rz;
        }

        // walk up the tree: G = T_anc @ G, ancestors fetched via shfl (max depth 5)
        float G[12];
        #pragma unroll
        for (int k = 0; k < 12; k++) G[k] = T[k];
        int a = (j < J) ? c_par[j] : -1;

        #pragma unroll
        for (int step = 0; step < 5; step++) {
            int srcLane = (a >= 0) ? a : 0;
            float L[12];
            #pragma unroll
            for (int k = 0; k < 12; k++)
                L[k] = __shfl_sync(0xffffffffu, T[k], srcLane);
            if (a >= 0) {
                float N[12];
                #pragma unroll
                for (int r = 0; r < 3; r++) {
                    float l0 = L[r*4+0], l1 = L[r*4+1], l2 = L[r*4+2], l3 = L[r*4+3];
                    N[r*4+0] = l0 * G[0] + l1 * G[4] + l2 * G[8];
                    N[r*4+1] = l0 * G[1] + l1 * G[5] + l2 * G[9];
                    N[r*4+2] = l0 * G[2] + l1 * G[6] + l2 * G[10];
                    N[r*4+3] = l0 * G[3] + l1 * G[7] + l2 * G[11] + l3;
                }
                #pragma unroll
                for (int k = 0; k < 12; k++) G[k] = N[k];
                a = c_par[a];
            }
        }

        if (j < J) {
            float pjx = G[3], pjy = G[7], pjz = G[11];
            float jx = jr[j*3+0], jy = jr[j*3+1], jz = jr[j*3+2];
            float tcx = G[0]*jx + G[1]*jy + G[2]*jz;
            float tcy = G[4]*jx + G[5]*jy + G[6]*jz;
            float tcz = G[8]*jx + G[9]*jy + G[10]*jz;
            G[3] -= tcx; G[7] -= tcy; G[11] -= tcz;
            #pragma unroll
            for (int k = 0; k < 12; k++) sA[j * 12 + k] = G[k];

            float c0 = 0.0035f * scl[0];
            float ox = loc[0] + 0.1f * tanhf(disp[0]);
            float oy = loc[1] + 0.1f * tanhf(disp[1]);
            float oz = loc[2] + 0.1f * tanhf(disp[2]);
            if (blockIdx.x == 0) {
                out[jointsOff + j*3 + 0] = c0 * pjx + ox;
                out[jointsOff + j*3 + 1] = c0 * pjy + oy;
                out[jointsOff + j*3 + 2] = c0 * pjz + oz;
            }
            if (j == 0) {
                sC[0] = c0; sC[1] = ox; sC[2] = oy; sC[3] = oz;
                if (blockIdx.x == 0) {
                    out[scaleOff] = scl[0];
                    out[dispOff + 0] = disp[0];
                    out[dispOff + 1] = disp[1];
                    out[dispOff + 2] = disp[2];
                }
            }
        }
    }

    // ================= stage skinning weights (all threads) =================
    {
        int nf = nv * J;
        const float4* src4 = reinterpret_cast<const float4*>(skin + vbase * J);
        float4* dst4 = reinterpret_cast<float4*>(sW);
        int n4 = nf >> 2;
        for (int k = tid; k < n4; k += BLK) dst4[k] = src4[k];
        for (int k = (n4 << 2) + tid; k < nf; k += BLK) sW[k] = skin[vbase * J + k];
    }
    __syncthreads();

    // ================= per-vertex LBS: 4 interleaved vertices/thread =================
    float x[VPT], y[VPT], z[VPT];
    bool valid[VPT];
    long long vv[VPT];

    #pragma unroll
    for (int i = 0; i < VPT; i++) {
        int lv = tid + i * BLK;
        valid[i] = (lv < nv);
        long long v = vbase + lv;
        long long vc = valid[i] ? v : (long long)(V - 1);
        vv[i] = v;
        float a0 = la[vc*3+0], a1 = la[vc*3+1], a2 = la[vc*3+2];
        x[i] = vt[vc*3+0] + 0.1f * tanhf(a0);
        y[i] = vt[vc*3+1] + 0.1f * tanhf(a1);
        z[i] = vt[vc*3+2] + 0.1f * tanhf(a2);
        if (valid[i]) {   // local_adjust passthrough, already in registers
            out[laOff + v*3 + 0] = a0;
            out[laOff + v*3 + 1] = a1;
            out[laOff + v*3 + 2] = a2;
        }
    }

    float p0[VPT], p1[VPT], p2[VPT];
    #pragma unroll
    for (int i = 0; i < VPT; i++) { p0[i] = 0.f; p1[i] = 0.f; p2[i] = 0.f; }

    #pragma unroll
    for (int j = 0; j < J; j++) {
        float4 a0 = *reinterpret_cast<const float4*>(sA + j*12 + 0);
        float4 a1 = *reinterpret_cast<const float4*>(sA + j*12 + 4);
        float4 a2 = *reinterpret_cast<const float4*>(sA + j*12 + 8);
        #pragma unroll
        for (int i = 0; i < VPT; i++) {
            float wj = sW[(tid + i * BLK) * J + j];
            float d0 = fmaf(a0.x, x[i], fmaf(a0.y, y[i], fmaf(a0.z, z[i], a0.w)));
            float d1 = fmaf(a1.x, x[i], fmaf(a1.y, y[i], fmaf(a1.z, z[i], a1.w)));
            float d2 = fmaf(a2.x, x[i], fmaf(a2.y, y[i], fmaf(a2.z, z[i], a2.w)));
            p0[i] = fmaf(wj, d0, p0[i]);
            p1[i] = fmaf(wj, d1, p1[i]);
            p2[i] = fmaf(wj, d2, p2[i]);
        }
    }

    float cc = sC[0], ox = sC[1], oy = sC[2], oz = sC[3];
    long long stride = 3LL * V;

    #pragma unroll
    for (int i = 0; i < VPT; i++) {
        if (!valid[i]) continue;
        float o0 = fmaf(cc, p0[i], ox);
        float o1 = fmaf(cc, p1[i], oy);
        float o2 = fmaf(cc, p2[i], oz);
        long long vb = vv[i] * 3;
        for (int b = 0; b < B; b++) {
            long long o = (long long)b * stride + vb;
            out[o + 0] = o0; out[o + 1] = o1; out[o + 2] = o2;
        }
    }
}

extern "C" void kernel_launch(void* const* d_in, const int* in_sizes, int n_in,
                              void* d_out, int out_size)
{
    const float* vt   = (const float*)d_in[0];
    const float* skin = (const float*)d_in[1];
    const float* jr   = (const float*)d_in[2];
    const float* j0   = (const float*)d_in[3];
    const float* j1   = (const float*)d_in[4];
    const float* j2   = (const float*)d_in[5];
    const float* j3   = (const float*)d_in[6];
    const float* j4   = (const float*)d_in[7];
    const float* j5   = (const float*)d_in[8];
    const float* j12  = (const float*)d_in[9];
    const float* j13  = (const float*)d_in[10];
    const float* la   = (const float*)d_in[11];
    const float* disp = (const float*)d_in[12];
    const float* scl  = (const float*)d_in[13];
    const float* loc  = (const float*)d_in[14];

    int V = in_sizes[0] / 3;
    long long tail = 2LL * (3 * J) + 1 + 3;              // pose + joints + scale + disp
    long long B = ((long long)out_size - tail - 3LL * V) / (3LL * V);

    long long poseOff   = B * 3LL * V;
    long long jointsOff = poseOff + 3 * J;
    long long scaleOff  = jointsOff + 3 * J;
    long long dispOff   = scaleOff + 1;
    long long laOff     = dispOff + 3;

    float* out = (float*)d_out;

    int blocks = (V + VPB - 1) / VPB;
    k_fused<<<blocks, BLK>>>(vt, skin, jr, j0, j1, j2, j3, j4, j5, j12, j13,
                             la, disp, scl, loc, out, V, (int)B,
                             poseOff, jointsOff, scaleOff, dispOff, laOff);
}

// round 3
// speedup vs baseline: 1.1705x; 1.1705x over previous
#include <cuda_runtime.h>
#include <math.h>

#define J 23
#define BLK 256
#define VPT 2
#define VPB (BLK * VPT)   // 512 vertices per block

__device__ __constant__ int c_par[J] = {-1, 0, 1, 1, 3, 4, 5, 4, 7, 4, 9, 1, 11, 12, 13, 12, 15, 12, 17, 0, 19, 0, 21};

__global__ __launch_bounds__(BLK) void k_fused(
    const float* __restrict__ vt, const float* __restrict__ skin,
    const float* __restrict__ jr,
    const float* __restrict__ j0, const float* __restrict__ j1,
    const float* __restrict__ j2, const float* __restrict__ j3,
    const float* __restrict__ j4, const float* __restrict__ j5,
    const float* __restrict__ j12, const float* __restrict__ j13,
    const float* __restrict__ la, const float* __restrict__ disp,
    const float* __restrict__ scl, const float* __restrict__ loc,
    float* __restrict__ out,
    int V, int B,
    long long poseOff, long long jointsOff, long long scaleOff,
    long long dispOff, long long laOff)
{
    __shared__ __align__(16) float sW[VPB * J];   // 47104 B
    __shared__ __align__(16) float sA[J * 12];    // blended transforms
    __shared__ float sC[4];                       // c, ox, oy, oz

    const int tid = threadIdx.x;
    const long long vbase = (long long)blockIdx.x * VPB;
    const int nv = min(VPB, V - (int)vbase);
    const float PI = 3.14159265358979323846f;

    // ================= pose / kinematics (warp 0 only; other warps go stage) ====
    if (tid < 32) {
        int j = tid;
        float T[12];
        #pragma unroll
        for (int k = 0; k < 12; k++) T[k] = 0.f;

        if (j < J) {
            float amp = 0.f, sy = 1.f, sz = 1.f;
            const float* src = nullptr;
            switch (j) {
                case 0:  amp = PI / 2.f; src = j0;  break;
                case 1:  amp = PI / 4.f; src = j1;  break;
                case 2:  amp = PI / 9.f; src = j2;  break;
                case 3:  amp = PI / 3.f; src = j3;  break;
                case 11: amp = PI / 3.f; src = j3;  sy = -1.f; sz = -1.f; break;
                case 4:  amp = PI / 3.f; src = j4;  break;
                case 5:  amp = PI / 3.f; src = j5;  break;
                case 12: amp = PI / 3.f; src = j12; break;
                case 13: amp = PI / 3.f; src = j13; break;
            }
            float px = 0.f, py = 0.f, pz = 0.f;
            if (src) {
                px = amp * tanhf(src[0]);
                py = amp * sy * tanhf(src[1]);
                pz = amp * sz * tanhf(src[2]);
            }
            if (blockIdx.x == 0) {
                out[poseOff + j * 3 + 0] = px;
                out[poseOff + j * 3 + 1] = py;
                out[poseOff + j * 3 + 2] = pz;
            }

            float ang = sqrtf(px * px + py * py + pz * pz + 1e-12f);
            float inv = 1.f / ang;
            float x = px * inv, y = py * inv, z = pz * inv;
            float s = sinf(ang), c = cosf(ang), t = 1.f - c;

            int p = c_par[j];
            float rx = jr[j * 3 + 0] - (p >= 0 ? jr[p * 3 + 0] : 0.f);
            float ry = jr[j * 3 + 1] - (p >= 0 ? jr[p * 3 + 1] : 0.f);
            float rz = jr[j * 3 + 2] - (p >= 0 ? jr[p * 3 + 2] : 0.f);

            T[0] = 1.f + t * (-(y * y + z * z));
            T[1] = -s * z + t * (x * y);
            T[2] =  s * y + t * (x * z);
            T[3] = rx;
            T[4] =  s * z + t * (x * y);
            T[5] = 1.f + t * (-(x * x + z * z));
            T[6] = -s * x + t * (y * z);
            T[7] = ry;
            T[8] = -s * y + t * (x * z);
            T[9] =  s * x + t * (y * z);
            T[10] = 1.f + t * (-(x * x + y * y));
            T[11] = rz;
        }

        // walk up the tree: G = T_anc @ G, ancestors fetched via shfl (max depth 5)
        float G[12];
        #pragma unroll
        for (int k = 0; k < 12; k++) G[k] = T[k];
        int a = (j < J) ? c_par[j] : -1;

        #pragma unroll
        for (int step = 0; step < 5; step++) {
            int srcLane = (a >= 0) ? a : 0;
            float L[12];
            #pragma unroll
            for (int k = 0; k < 12; k++)
                L[k] = __shfl_sync(0xffffffffu, T[k], srcLane);
            if (a >= 0) {
                float N[12];
                #pragma unroll
                for (int r = 0; r < 3; r++) {
                    float l0 = L[r*4+0], l1 = L[r*4+1], l2 = L[r*4+2], l3 = L[r*4+3];
                    N[r*4+0] = l0 * G[0] + l1 * G[4] + l2 * G[8];
                    N[r*4+1] = l0 * G[1] + l1 * G[5] + l2 * G[9];
                    N[r*4+2] = l0 * G[2] + l1 * G[6] + l2 * G[10];
                    N[r*4+3] = l0 * G[3] + l1 * G[7] + l2 * G[11] + l3;
                }
                #pragma unroll
                for (int k = 0; k < 12; k++) G[k] = N[k];
                a = c_par[a];
            }
        }

        if (j < J) {
            float pjx = G[3], pjy = G[7], pjz = G[11];
            float jx = jr[j*3+0], jy = jr[j*3+1], jz = jr[j*3+2];
            float tcx = G[0]*jx + G[1]*jy + G[2]*jz;
            float tcy = G[4]*jx + G[5]*jy + G[6]*jz;
            float tcz = G[8]*jx + G[9]*jy + G[10]*jz;
            G[3] -= tcx; G[7] -= tcy; G[11] -= tcz;
            #pragma unroll
            for (int k = 0; k < 12; k++) sA[j * 12 + k] = G[k];

            float c0 = 0.0035f * scl[0];
            float ox = loc[0] + 0.1f * tanhf(disp[0]);
            float oy = loc[1] + 0.1f * tanhf(disp[1]);
            float oz = loc[2] + 0.1f * tanhf(disp[2]);
            if (blockIdx.x == 0) {
                out[jointsOff + j*3 + 0] = c0 * pjx + ox;
                out[jointsOff + j*3 + 1] = c0 * pjy + oy;
                out[jointsOff + j*3 + 2] = c0 * pjz + oz;
            }
            if (j == 0) {
                sC[0] = c0; sC[1] = ox; sC[2] = oy; sC[3] = oz;
                if (blockIdx.x == 0) {
                    out[scaleOff] = scl[0];
                    out[dispOff + 0] = disp[0];
                    out[dispOff + 1] = disp[1];
                    out[dispOff + 2] = disp[2];
                }
            }
        }
    }

    // ================= stage skinning weights (all threads) =================
    {
        int nf = nv * J;
        const float4* src4 = reinterpret_cast<const float4*>(skin + vbase * J);
        float4* dst4 = reinterpret_cast<float4*>(sW);
        int n4 = nf >> 2;
        for (int k = tid; k < n4; k += BLK) dst4[k] = src4[k];
        for (int k = (n4 << 2) + tid; k < nf; k += BLK) sW[k] = skin[vbase * J + k];
    }
    __syncthreads();

    // ================= per-vertex LBS: 2 interleaved vertices/thread =================
    float x[VPT], y[VPT], z[VPT];
    bool valid[VPT];
    long long vv[VPT];

    #pragma unroll
    for (int i = 0; i < VPT; i++) {
        int lv = tid + i * BLK;
        valid[i] = (lv < nv);
        long long v = vbase + lv;
        long long vc = valid[i] ? v : (long long)(V - 1);
        vv[i] = v;
        float a0 = la[vc*3+0], a1 = la[vc*3+1], a2 = la[vc*3+2];
        x[i] = vt[vc*3+0] + 0.1f * tanhf(a0);
        y[i] = vt[vc*3+1] + 0.1f * tanhf(a1);
        z[i] = vt[vc*3+2] + 0.1f * tanhf(a2);
        if (valid[i]) {   // local_adjust passthrough, already in registers
            out[laOff + v*3 + 0] = a0;
            out[laOff + v*3 + 1] = a1;
            out[laOff + v*3 + 2] = a2;
        }
    }

    float p0[VPT], p1[VPT], p2[VPT];
    #pragma unroll
    for (int i = 0; i < VPT; i++) { p0[i] = 0.f; p1[i] = 0.f; p2[i] = 0.f; }

    #pragma unroll
    for (int j = 0; j < J; j++) {
        float4 a0 = *reinterpret_cast<const float4*>(sA + j*12 + 0);
        float4 a1 = *reinterpret_cast<const float4*>(sA + j*12 + 4);
        float4 a2 = *reinterpret_cast<const float4*>(sA + j*12 + 8);
        #pragma unroll
        for (int i = 0; i < VPT; i++) {
            float wj = sW[(tid + i * BLK) * J + j];
            float d0 = fmaf(a0.x, x[i], fmaf(a0.y, y[i], fmaf(a0.z, z[i], a0.w)));
            float d1 = fmaf(a1.x, x[i], fmaf(a1.y, y[i], fmaf(a1.z, z[i], a1.w)));
            float d2 = fmaf(a2.x, x[i], fmaf(a2.y, y[i], fmaf(a2.z, z[i], a2.w)));
            p0[i] = fmaf(wj, d0, p0[i]);
            p1[i] = fmaf(wj, d1, p1[i]);
            p2[i] = fmaf(wj, d2, p2[i]);
        }
    }

    float cc = sC[0], ox = sC[1], oy = sC[2], oz = sC[3];
    long long stride = 3LL * V;

    #pragma unroll
    for (int i = 0; i < VPT; i++) {
        if (!valid[i]) continue;
        float o0 = fmaf(cc, p0[i], ox);
        float o1 = fmaf(cc, p1[i], oy);
        float o2 = fmaf(cc, p2[i], oz);
        long long vb = vv[i] * 3;
        for (int b = 0; b < B; b++) {
            long long o = (long long)b * stride + vb;
            out[o + 0] = o0; out[o + 1] = o1; out[o + 2] = o2;
        }
    }
}

extern "C" void kernel_launch(void* const* d_in, const int* in_sizes, int n_in,
                              void* d_out, int out_size)
{
    const float* vt   = (const float*)d_in[0];
    const float* skin = (const float*)d_in[1];
    const float* jr   = (const float*)d_in[2];
    const float* j0   = (const float*)d_in[3];
    const float* j1   = (const float*)d_in[4];
    const float* j2   = (const float*)d_in[5];
    const float* j3   = (const float*)d_in[6];
    const float* j4   = (const float*)d_in[7];
    const float* j5   = (const float*)d_in[8];
    const float* j12  = (const float*)d_in[9];
    const float* j13  = (const float*)d_in[10];
    const float* la   = (const float*)d_in[11];
    const float* disp = (const float*)d_in[12];
    const float* scl  = (const float*)d_in[13];
    const float* loc  = (const float*)d_in[14];

    int V = in_sizes[0] / 3;
    long long tail = 2LL * (3 * J) + 1 + 3;              // pose + joints + scale + disp
    long long B = ((long long)out_size - tail - 3LL * V) / (3LL * V);

    long long poseOff   = B * 3LL * V;
    long long jointsOff = poseOff + 3 * J;
    long long scaleOff  = jointsOff + 3 * J;
    long long dispOff   = scaleOff + 1;
    long long laOff     = dispOff + 3;

    float* out = (float*)d_out;

    int blocks = (V + VPB - 1) / VPB;
    k_fused<<<blocks, BLK>>>(vt, skin, jr, j0, j1, j2, j3, j4, j5, j12, j13,
                             la, disp, scl, loc, out, V, (int)B,
                             poseOff, jointsOff, scaleOff, dispOff, laOff);
}